// round 1
// baseline (speedup 1.0000x reference)
#include <cuda_runtime.h>
#include <cuda_bf16.h>
#include <cstdint>

// ---------------- problem constants ----------------
#define D_ 2048
#define B_ 4
#define T_ 2048
#define M_ (B_*T_)          // 8192 rows of activations

#define MD ((size_t)M_*(size_t)D_)   // 16,777,216
#define DD ((size_t)D_*(size_t)D_)   //  4,194,304

// ---------------- scratch (static device globals — allocation-free) --------
__device__ __align__(256) __nv_bfloat16 g_xh[3*MD];   // mixed activations hi (k,v,r)
__device__ __align__(256) __nv_bfloat16 g_xl[3*MD];   // mixed activations lo
__device__ __align__(256) __nv_bfloat16 g_wh[4*DD];   // weights hi (Wk,Wv,Wr,Wo)
__device__ __align__(256) __nv_bfloat16 g_wl[4*DD];   // weights lo
__device__ __align__(256) float         g_kvr[3*MD];  // k, v, r (fp32 GEMM outputs)
__device__ __align__(256) __nv_bfloat16 g_uh[MD];     // wkv*sigmoid(r) hi
__device__ __align__(256) __nv_bfloat16 g_ul[MD];     // wkv*sigmoid(r) lo

// ---------------- weight hi/lo split ----------------
__global__ void wconv_kernel(const float* __restrict__ W0, const float* __restrict__ W1,
                             const float* __restrict__ W2, const float* __restrict__ W3)
{
    size_t i = (size_t)blockIdx.x * blockDim.x + threadIdx.x;
    if (i >= 4*DD) return;
    size_t which = i / DD;
    const float* Ws = (which == 0) ? W0 : (which == 1) ? W1 : (which == 2) ? W2 : W3;
    float w = Ws[i - which*DD];
    __nv_bfloat16 h = __float2bfloat16(w);
    g_wh[i] = h;
    g_wl[i] = __float2bfloat16(w - __bfloat162float(h));
}

// ---------------- time-shift mix + hi/lo split ----------------
__global__ void mix_kernel(const float* __restrict__ x,
                           const float* __restrict__ mk,
                           const float* __restrict__ mv,
                           const float* __restrict__ mr)
{
    size_t i = (size_t)blockIdx.x * blockDim.x + threadIdx.x;
    if (i >= MD) return;
    int d = (int)(i & (size_t)(D_-1));
    int t = (int)((i / D_) & (size_t)(T_-1));
    float xv = x[i];
    float lx = (t > 0) ? x[i - D_] : 0.0f;
    float dx = xv - lx;

    float a = fmaf(dx, mk[d], lx);                 // x*m + lx*(1-m)
    __nv_bfloat16 h = __float2bfloat16(a);
    g_xh[i]        = h;
    g_xl[i]        = __float2bfloat16(a - __bfloat162float(h));

    a = fmaf(dx, mv[d], lx);
    h = __float2bfloat16(a);
    g_xh[MD + i]   = h;
    g_xl[MD + i]   = __float2bfloat16(a - __bfloat162float(h));

    a = fmaf(dx, mr[d], lx);
    h = __float2bfloat16(a);
    g_xh[2*MD + i] = h;
    g_xl[2*MD + i] = __float2bfloat16(a - __bfloat162float(h));
}

// ---------------- bf16-split GEMM: C[M,N] = A[M,K] * B[N,K]^T ----------------
// C = Ah*Bh + Ah*Bl + Al*Bh  (fp32 accum) — near-fp32 accuracy.
#define BM 128
#define BN 128
#define BK 32

__device__ __forceinline__ uint32_t cvta_s(const void* p) {
    return (uint32_t)__cvta_generic_to_shared(p);
}
__device__ __forceinline__ void cp16(void* s, const void* g) {
    asm volatile("cp.async.cg.shared.global [%0], [%1], 16;\n"
                 :: "r"(cvta_s(s)), "l"(g));
}
// swizzled element offset in a [rows][BK] bf16 tile; 16B chunks XOR'd so that
// both the cp.async stores and the ldmatrix reads are bank-conflict-free.
__device__ __forceinline__ int swoff(int r, int c) {
    return r*BK + ((c ^ ((r >> 1) & 3)) << 3);
}

#define MMA_BF16(cc, aa, bb)                                                    \
    asm volatile("mma.sync.aligned.m16n8k16.row.col.f32.bf16.bf16.f32 "          \
                 "{%0,%1,%2,%3},{%4,%5,%6,%7},{%8,%9},{%0,%1,%2,%3};\n"          \
                 : "+f"(cc[0]), "+f"(cc[1]), "+f"(cc[2]), "+f"(cc[3])            \
                 : "r"(aa[0]), "r"(aa[1]), "r"(aa[2]), "r"(aa[3]),               \
                   "r"(bb[0]), "r"(bb[1]))

__global__ void __launch_bounds__(256, 1)
gemm_kernel(const __nv_bfloat16* __restrict__ Ah, const __nv_bfloat16* __restrict__ Al,
            const __nv_bfloat16* __restrict__ Bh, const __nv_bfloat16* __restrict__ Bl,
            float* __restrict__ C, int M, int N, int K)
{
    extern __shared__ __align__(16) char smem_raw[];
    __nv_bfloat16* sAh = (__nv_bfloat16*)smem_raw;          // [2][BM*BK]
    __nv_bfloat16* sAl = sAh + 2*BM*BK;
    __nv_bfloat16* sBh = sAl + 2*BM*BK;
    __nv_bfloat16* sBl = sBh + 2*BM*BK;

    const int tid  = threadIdx.x;
    const int lane = tid & 31;
    const int warp = tid >> 5;
    const int wm   = warp >> 2;   // 0..1  (64 rows each)
    const int wn   = warp & 3;    // 0..3  (32 cols each)

    const int bm = blockIdx.y * BM;
    const int bn = blockIdx.x * BN;

    float c[4][4][4];
    #pragma unroll
    for (int i = 0; i < 4; i++)
        #pragma unroll
        for (int j = 0; j < 4; j++)
            #pragma unroll
            for (int q = 0; q < 4; q++) c[i][j][q] = 0.0f;

    const __nv_bfloat16* gbase[4] = { Ah + (size_t)bm*K, Al + (size_t)bm*K,
                                      Bh + (size_t)bn*K, Bl + (size_t)bn*K };
    __nv_bfloat16* sbase[4] = { sAh, sAl, sBh, sBl };

    auto issue_loads = [&](int s, int bi) {
        int k0 = s * BK;
        #pragma unroll
        for (int op = 0; op < 4; op++) {
            #pragma unroll
            for (int q = 0; q < 2; q++) {
                int cid = tid + q*256;          // 512 16B-chunks per operand tile
                int rr = cid >> 2, cc = cid & 3;
                const __nv_bfloat16* g = gbase[op] + (size_t)rr*K + k0 + cc*8;
                __nv_bfloat16* sd = sbase[op] + bi*(BM*BK) + swoff(rr, cc);
                cp16(sd, g);
            }
        }
        asm volatile("cp.async.commit_group;\n");
    };

    auto compute_stage = [&](int bi) {
        #pragma unroll
        for (int kk = 0; kk < 2; kk++) {
            uint32_t bhf[4][2], blf[4][2];
            #pragma unroll
            for (int p = 0; p < 2; p++) {
                int rr = wn*32 + p*16 + (lane & 15);
                int cc = kk*2 + (lane >> 4);
                uint32_t r0, r1, r2, r3, ad;
                ad = cvta_s(sBh + bi*(BM*BK) + swoff(rr, cc));
                asm volatile("ldmatrix.sync.aligned.m8n8.x4.shared.b16 {%0,%1,%2,%3},[%4];\n"
                             : "=r"(r0), "=r"(r1), "=r"(r2), "=r"(r3) : "r"(ad));
                bhf[2*p][0] = r0; bhf[2*p][1] = r2;
                bhf[2*p+1][0] = r1; bhf[2*p+1][1] = r3;
                ad = cvta_s(sBl + bi*(BM*BK) + swoff(rr, cc));
                asm volatile("ldmatrix.sync.aligned.m8n8.x4.shared.b16 {%0,%1,%2,%3},[%4];\n"
                             : "=r"(r0), "=r"(r1), "=r"(r2), "=r"(r3) : "r"(ad));
                blf[2*p][0] = r0; blf[2*p][1] = r2;
                blf[2*p+1][0] = r1; blf[2*p+1][1] = r3;
            }
            #pragma unroll
            for (int mt = 0; mt < 4; mt++) {
                int rr = wm*64 + mt*16 + (lane & 15);
                int cc = kk*2 + (lane >> 4);
                uint32_t ah[4], al4[4], ad;
                ad = cvta_s(sAh + bi*(BM*BK) + swoff(rr, cc));
                asm volatile("ldmatrix.sync.aligned.m8n8.x4.shared.b16 {%0,%1,%2,%3},[%4];\n"
                             : "=r"(ah[0]), "=r"(ah[1]), "=r"(ah[2]), "=r"(ah[3]) : "r"(ad));
                ad = cvta_s(sAl + bi*(BM*BK) + swoff(rr, cc));
                asm volatile("ldmatrix.sync.aligned.m8n8.x4.shared.b16 {%0,%1,%2,%3},[%4];\n"
                             : "=r"(al4[0]), "=r"(al4[1]), "=r"(al4[2]), "=r"(al4[3]) : "r"(ad));
                #pragma unroll
                for (int nt = 0; nt < 4; nt++) {
                    MMA_BF16(c[mt][nt], ah,  bhf[nt]);
                    MMA_BF16(c[mt][nt], ah,  blf[nt]);
                    MMA_BF16(c[mt][nt], al4, bhf[nt]);
                }
            }
        }
    };

    const int NS = K / BK;
    issue_loads(0, 0);
    asm volatile("cp.async.wait_group 0;\n");
    __syncthreads();

    for (int s = 0; s < NS; s++) {
        int bi = s & 1;
        if (s + 1 < NS) issue_loads(s + 1, bi ^ 1);
        compute_stage(bi);
        if (s + 1 < NS) asm volatile("cp.async.wait_group 0;\n");
        __syncthreads();
    }

    // epilogue
    #pragma unroll
    for (int mt = 0; mt < 4; mt++) {
        #pragma unroll
        for (int nt = 0; nt < 4; nt++) {
            int row = bm + wm*64 + mt*16 + (lane >> 2);
            int col = bn + wn*32 + nt*8 + (lane & 3)*2;
            *reinterpret_cast<float2*>(C + (size_t)row*N + col) =
                make_float2(c[mt][nt][0], c[mt][nt][1]);
            *reinterpret_cast<float2*>(C + (size_t)(row+8)*N + col) =
                make_float2(c[mt][nt][2], c[mt][nt][3]);
        }
    }
}

// ---------------- WKV scan (numerically stable, matches reference) ----------
__global__ void wkv_scan_kernel(const float* __restrict__ kk, const float* __restrict__ vv,
                                const float* __restrict__ rr,
                                const float* __restrict__ td, const float* __restrict__ tf)
{
    int g = blockIdx.x * 32 + threadIdx.x;      // 0 .. B_*D_-1
    int b = g >> 11;                            // D_ = 2048
    int d = g & (D_ - 1);
    float w = expf(td[d]);                      // exp(time_decay)
    float u = tf[d];

    float alpha = 0.0f, beta = 0.0f, eps = -1e30f;
    size_t base = (size_t)b * T_ * D_ + d;

    #pragma unroll 4
    for (int t = 0; t < T_; t++) {
        size_t idx = base + (size_t)t * D_;
        float kt = kk[idx];
        float vt = vv[idx];
        float rt = rr[idx];

        float ww  = u + kt;
        float tau = fmaxf(eps, ww);
        float e1  = __expf(eps - tau);
        float e2  = __expf(ww - tau);
        float out = (e1*alpha + e2*vt) / (e1*beta + e2);

        float ww2  = eps - w;
        float tau2 = fmaxf(ww2, kt);
        float e1b  = __expf(ww2 - tau2);
        float e2b  = __expf(kt - tau2);
        alpha = e1b*alpha + e2b*vt;
        beta  = e1b*beta + e2b;
        eps   = tau2;

        float sr = 1.0f / (1.0f + __expf(-rt));
        float uo = out * sr;
        __nv_bfloat16 h = __float2bfloat16(uo);
        g_uh[idx] = h;
        g_ul[idx] = __float2bfloat16(uo - __bfloat162float(h));
    }
}

// ---------------- launch ----------------
extern "C" void kernel_launch(void* const* d_in, const int* in_sizes, int n_in,
                              void* d_out, int out_size)
{
    const float* x  = (const float*)d_in[0];
    const float* td = (const float*)d_in[1];
    const float* tf = (const float*)d_in[2];
    const float* mk = (const float*)d_in[3];
    const float* mv = (const float*)d_in[4];
    const float* mr = (const float*)d_in[5];
    const float* Wk = (const float*)d_in[6];
    const float* Wv = (const float*)d_in[7];
    const float* Wr = (const float*)d_in[8];
    const float* Wo = (const float*)d_in[9];
    float* out = (float*)d_out;

    __nv_bfloat16 *xh, *xl, *wh, *wl, *uh, *ul;
    float* kvr;
    cudaGetSymbolAddress((void**)&xh,  g_xh);
    cudaGetSymbolAddress((void**)&xl,  g_xl);
    cudaGetSymbolAddress((void**)&wh,  g_wh);
    cudaGetSymbolAddress((void**)&wl,  g_wl);
    cudaGetSymbolAddress((void**)&kvr, g_kvr);
    cudaGetSymbolAddress((void**)&uh,  g_uh);
    cudaGetSymbolAddress((void**)&ul,  g_ul);

    const int GEMM_SMEM = 2 * 4 * BM * BK * (int)sizeof(__nv_bfloat16);  // 65536
    cudaFuncSetAttribute(gemm_kernel, cudaFuncAttributeMaxDynamicSharedMemorySize, GEMM_SMEM);

    wconv_kernel<<<(unsigned)((4*DD + 255) / 256), 256>>>(Wk, Wv, Wr, Wo);
    mix_kernel<<<(unsigned)((MD + 255) / 256), 256>>>(x, mk, mv, mr);

    dim3 grid(D_ / BN, M_ / BM);   // (16, 64)
    for (int i = 0; i < 3; i++) {
        gemm_kernel<<<grid, 256, GEMM_SMEM>>>(xh + (size_t)i*MD, xl + (size_t)i*MD,
                                              wh + (size_t)i*DD, wl + (size_t)i*DD,
                                              kvr + (size_t)i*MD, M_, D_, D_);
    }

    wkv_scan_kernel<<<(B_*D_)/32, 32>>>(kvr, kvr + MD, kvr + 2*MD, td, tf);

    gemm_kernel<<<grid, 256, GEMM_SMEM>>>(uh, ul, wh + 3*DD, wl + 3*DD,
                                          out, M_, D_, D_);
}

// round 4
// speedup vs baseline: 1.5929x; 1.5929x over previous
#include <cuda_runtime.h>
#include <cuda_bf16.h>
#include <cstdint>

// ---------------- problem constants ----------------
#define D_ 2048
#define B_ 4
#define T_ 2048
#define M_ (B_*T_)          // 8192

#define MD ((size_t)M_*(size_t)D_)   // 16,777,216
#define DD ((size_t)D_*(size_t)D_)   //  4,194,304

#define NCH 32
#define CL  (T_/NCH)                 // 64
#define BDN (B_*NCH*D_)              // 262,144

// ---------------- scratch (static device globals — allocation-free) --------
__device__ __align__(256) __nv_bfloat16 g_xh[3*MD];
__device__ __align__(256) __nv_bfloat16 g_xl[3*MD];
__device__ __align__(256) __nv_bfloat16 g_wh[4*DD];
__device__ __align__(256) __nv_bfloat16 g_wl[4*DD];
__device__ __align__(256) float         g_kvr[3*MD];
__device__ __align__(256) __nv_bfloat16 g_uh[MD];
__device__ __align__(256) __nv_bfloat16 g_ul[MD];
__device__ __align__(256) float         g_agg[3*BDN];   // chunk aggregates
__device__ __align__(256) float         g_car[3*BDN];   // chunk carry-ins

// ---------------- weight hi/lo split ----------------
__global__ void wconv_kernel(const float* __restrict__ W0, const float* __restrict__ W1,
                             const float* __restrict__ W2, const float* __restrict__ W3)
{
    size_t i = (size_t)blockIdx.x * blockDim.x + threadIdx.x;
    if (i >= 4*DD) return;
    size_t which = i / DD;
    const float* Ws = (which == 0) ? W0 : (which == 1) ? W1 : (which == 2) ? W2 : W3;
    float w = Ws[i - which*DD];
    __nv_bfloat16 h = __float2bfloat16(w);
    g_wh[i] = h;
    g_wl[i] = __float2bfloat16(w - __bfloat162float(h));
}

// ---------------- time-shift mix + hi/lo split ----------------
__global__ void mix_kernel(const float* __restrict__ x,
                           const float* __restrict__ mk,
                           const float* __restrict__ mv,
                           const float* __restrict__ mr)
{
    size_t i = (size_t)blockIdx.x * blockDim.x + threadIdx.x;
    if (i >= MD) return;
    int d = (int)(i & (size_t)(D_-1));
    int t = (int)((i / D_) & (size_t)(T_-1));
    float xv = x[i];
    float lx = (t > 0) ? x[i - D_] : 0.0f;
    float dx = xv - lx;

    float a = fmaf(dx, mk[d], lx);
    __nv_bfloat16 h = __float2bfloat16(a);
    g_xh[i]        = h;
    g_xl[i]        = __float2bfloat16(a - __bfloat162float(h));

    a = fmaf(dx, mv[d], lx);
    h = __float2bfloat16(a);
    g_xh[MD + i]   = h;
    g_xl[MD + i]   = __float2bfloat16(a - __bfloat162float(h));

    a = fmaf(dx, mr[d], lx);
    h = __float2bfloat16(a);
    g_xh[2*MD + i] = h;
    g_xl[2*MD + i] = __float2bfloat16(a - __bfloat162float(h));
}

// ---------------- bf16-split GEMM: C[M,N] = A[M,K] * B[N,K]^T ----------------
// C = Ah*Bh + Ah*Bl + Al*Bh  (fp32 accum) — near-fp32 accuracy.
#define BM 128
#define BN 128
#define BK 32

__device__ __forceinline__ uint32_t cvta_s(const void* p) {
    return (uint32_t)__cvta_generic_to_shared(p);
}
__device__ __forceinline__ void cp16(void* s, const void* g) {
    asm volatile("cp.async.cg.shared.global [%0], [%1], 16;\n"
                 :: "r"(cvta_s(s)), "l"(g));
}
__device__ __forceinline__ int swoff(int r, int c) {
    return r*BK + ((c ^ ((r >> 1) & 3)) << 3);
}

#define MMA_BF16(cc, aa, bb)                                                    \
    asm volatile("mma.sync.aligned.m16n8k16.row.col.f32.bf16.bf16.f32 "          \
                 "{%0,%1,%2,%3},{%4,%5,%6,%7},{%8,%9},{%0,%1,%2,%3};\n"          \
                 : "+f"(cc[0]), "+f"(cc[1]), "+f"(cc[2]), "+f"(cc[3])            \
                 : "r"(aa[0]), "r"(aa[1]), "r"(aa[2]), "r"(aa[3]),               \
                   "r"(bb[0]), "r"(bb[1]))

__global__ void __launch_bounds__(256, 2)   // <= 128 regs -> 2 CTAs/SM (occ 25%)
gemm_kernel(const __nv_bfloat16* __restrict__ Ah, const __nv_bfloat16* __restrict__ Al,
            const __nv_bfloat16* __restrict__ Bh, const __nv_bfloat16* __restrict__ Bl,
            float* __restrict__ C, int M, int N, int K)
{
    extern __shared__ __align__(16) char smem_raw[];
    __nv_bfloat16* sAh = (__nv_bfloat16*)smem_raw;          // [2][BM*BK]
    __nv_bfloat16* sAl = sAh + 2*BM*BK;
    __nv_bfloat16* sBh = sAl + 2*BM*BK;
    __nv_bfloat16* sBl = sBh + 2*BM*BK;

    const int tid  = threadIdx.x;
    const int lane = tid & 31;
    const int warp = tid >> 5;
    const int wm   = warp >> 2;   // 0..1  (64 rows each)
    const int wn   = warp & 3;    // 0..3  (32 cols each)

    const int bm = blockIdx.y * BM;
    const int bn = blockIdx.x * BN;

    float c[4][4][4];
    #pragma unroll
    for (int i = 0; i < 4; i++)
        #pragma unroll
        for (int j = 0; j < 4; j++)
            #pragma unroll
            for (int q = 0; q < 4; q++) c[i][j][q] = 0.0f;

    const __nv_bfloat16* gbase[4] = { Ah + (size_t)bm*K, Al + (size_t)bm*K,
                                      Bh + (size_t)bn*K, Bl + (size_t)bn*K };
    __nv_bfloat16* sbase[4] = { sAh, sAl, sBh, sBl };

    auto issue_loads = [&](int s, int bi) {
        int k0 = s * BK;
        #pragma unroll
        for (int op = 0; op < 4; op++) {
            #pragma unroll
            for (int q = 0; q < 2; q++) {
                int cid = tid + q*256;
                int rr = cid >> 2, cc = cid & 3;
                const __nv_bfloat16* g = gbase[op] + (size_t)rr*K + k0 + cc*8;
                __nv_bfloat16* sd = sbase[op] + bi*(BM*BK) + swoff(rr, cc);
                cp16(sd, g);
            }
        }
        asm volatile("cp.async.commit_group;\n");
    };

    auto compute_stage = [&](int bi) {
        #pragma unroll
        for (int kk = 0; kk < 2; kk++) {
            uint32_t bhf[4][2], blf[4][2];
            #pragma unroll
            for (int p = 0; p < 2; p++) {
                int rr = wn*32 + p*16 + (lane & 15);
                int cc = kk*2 + (lane >> 4);
                uint32_t r0, r1, r2, r3, ad;
                ad = cvta_s(sBh + bi*(BM*BK) + swoff(rr, cc));
                asm volatile("ldmatrix.sync.aligned.m8n8.x4.shared.b16 {%0,%1,%2,%3},[%4];\n"
                             : "=r"(r0), "=r"(r1), "=r"(r2), "=r"(r3) : "r"(ad));
                bhf[2*p][0] = r0; bhf[2*p][1] = r2;
                bhf[2*p+1][0] = r1; bhf[2*p+1][1] = r3;
                ad = cvta_s(sBl + bi*(BM*BK) + swoff(rr, cc));
                asm volatile("ldmatrix.sync.aligned.m8n8.x4.shared.b16 {%0,%1,%2,%3},[%4];\n"
                             : "=r"(r0), "=r"(r1), "=r"(r2), "=r"(r3) : "r"(ad));
                blf[2*p][0] = r0; blf[2*p][1] = r2;
                blf[2*p+1][0] = r1; blf[2*p+1][1] = r3;
            }
            #pragma unroll
            for (int mt = 0; mt < 4; mt++) {
                int rr = wm*64 + mt*16 + (lane & 15);
                int cc = kk*2 + (lane >> 4);
                uint32_t ah[4], al4[4], ad;
                ad = cvta_s(sAh + bi*(BM*BK) + swoff(rr, cc));
                asm volatile("ldmatrix.sync.aligned.m8n8.x4.shared.b16 {%0,%1,%2,%3},[%4];\n"
                             : "=r"(ah[0]), "=r"(ah[1]), "=r"(ah[2]), "=r"(ah[3]) : "r"(ad));
                ad = cvta_s(sAl + bi*(BM*BK) + swoff(rr, cc));
                asm volatile("ldmatrix.sync.aligned.m8n8.x4.shared.b16 {%0,%1,%2,%3},[%4];\n"
                             : "=r"(al4[0]), "=r"(al4[1]), "=r"(al4[2]), "=r"(al4[3]) : "r"(ad));
                #pragma unroll
                for (int nt = 0; nt < 4; nt++) {
                    MMA_BF16(c[mt][nt], ah,  bhf[nt]);
                    MMA_BF16(c[mt][nt], ah,  blf[nt]);
                    MMA_BF16(c[mt][nt], al4, bhf[nt]);
                }
            }
        }
    };

    const int NS = K / BK;
    issue_loads(0, 0);
    asm volatile("cp.async.wait_group 0;\n");
    __syncthreads();

    for (int s = 0; s < NS; s++) {
        int bi = s & 1;
        if (s + 1 < NS) issue_loads(s + 1, bi ^ 1);
        compute_stage(bi);
        if (s + 1 < NS) asm volatile("cp.async.wait_group 0;\n");
        __syncthreads();
    }

    // epilogue
    #pragma unroll
    for (int mt = 0; mt < 4; mt++) {
        #pragma unroll
        for (int nt = 0; nt < 4; nt++) {
            int row = bm + wm*64 + mt*16 + (lane >> 2);
            int col = bn + wn*32 + nt*8 + (lane & 3)*2;
            *reinterpret_cast<float2*>(C + (size_t)row*N + col) =
                make_float2(c[mt][nt][0], c[mt][nt][1]);
            *reinterpret_cast<float2*>(C + (size_t)(row+8)*N + col) =
                make_float2(c[mt][nt][2], c[mt][nt][3]);
        }
    }
}

// ============================================================================
// WKV parallel scan: 3 phases. Unnormalized state (A,B)=(e^eps a, e^eps b)
// obeys a LINEAR recurrence, so per-chunk transforms compose exactly:
//   eps_out = max(eps_in - w*CL, pe);  U_out = e^{-w*CL} U_in + P
// ============================================================================

// Phase 1: per-(b,d,chunk) local aggregate from identity (0,0,-inf).
__global__ void wkv_chunk_kernel(const float* __restrict__ kk, const float* __restrict__ vv,
                                 const float* __restrict__ td)
{
    int g  = blockIdx.x * 256 + threadIdx.x;    // 0 .. BDN-1
    int d  = g & (D_-1);
    int ch = (g >> 11) & (NCH-1);
    int b  = g >> 16;
    float w = expf(td[d]);

    float alpha = 0.0f, beta = 0.0f, eps = -1e30f;
    size_t base = ((size_t)b * T_ + (size_t)ch * CL) * D_ + d;

    #pragma unroll 4
    for (int i = 0; i < CL; i++) {
        size_t idx = base + (size_t)i * D_;
        float kt = kk[idx];
        float vt = vv[idx];
        float ww2  = eps - w;
        float tau2 = fmaxf(ww2, kt);
        float e1b  = __expf(ww2 - tau2);
        float e2b  = __expf(kt - tau2);
        alpha = e1b*alpha + e2b*vt;
        beta  = e1b*beta + e2b;
        eps   = tau2;
    }
    size_t o = ((size_t)b * NCH + ch) * D_ + d;
    g_agg[o]         = alpha;
    g_agg[BDN + o]   = beta;
    g_agg[2*BDN + o] = eps;
}

// Phase 2: sequential stitch over chunks per (b,d); writes per-chunk carry-in.
__global__ void wkv_stitch_kernel(const float* __restrict__ td)
{
    int g = blockIdx.x * 256 + threadIdx.x;     // 0 .. B_*D_-1
    int d = g & (D_-1);
    int b = g >> 11;
    float w  = expf(td[d]);
    float dl = -w * (float)CL;                  // log decay across one chunk

    float a = 0.0f, bt = 0.0f, e = -1e30f;
    #pragma unroll 4
    for (int ch = 0; ch < NCH; ch++) {
        size_t o = ((size_t)b * NCH + ch) * D_ + d;
        g_car[o]         = a;
        g_car[BDN + o]   = bt;
        g_car[2*BDN + o] = e;
        float pa = g_agg[o];
        float pb = g_agg[BDN + o];
        float pe = g_agg[2*BDN + o];
        float ein = e + dl;
        float ne  = fmaxf(ein, pe);
        float f1  = __expf(ein - ne);
        float f2  = __expf(pe - ne);
        a  = f1*a  + f2*pa;
        bt = f1*bt + f2*pb;
        e  = ne;
    }
}

// Phase 3: replay each chunk from its carry, produce wkv*sigmoid(r) hi/lo.
__global__ void wkv_apply_kernel(const float* __restrict__ kk, const float* __restrict__ vv,
                                 const float* __restrict__ rr,
                                 const float* __restrict__ td, const float* __restrict__ tf)
{
    int g  = blockIdx.x * 256 + threadIdx.x;
    int d  = g & (D_-1);
    int ch = (g >> 11) & (NCH-1);
    int b  = g >> 16;
    float w = expf(td[d]);
    float u = tf[d];

    size_t o = ((size_t)b * NCH + ch) * D_ + d;
    float alpha = g_car[o];
    float beta  = g_car[BDN + o];
    float eps   = g_car[2*BDN + o];

    size_t base = ((size_t)b * T_ + (size_t)ch * CL) * D_ + d;

    #pragma unroll 4
    for (int i = 0; i < CL; i++) {
        size_t idx = base + (size_t)i * D_;
        float kt = kk[idx];
        float vt = vv[idx];
        float rt = rr[idx];

        float ww  = u + kt;
        float tau = fmaxf(eps, ww);
        float e1  = __expf(eps - tau);
        float e2  = __expf(ww - tau);
        float out = (e1*alpha + e2*vt) / (e1*beta + e2);

        float ww2  = eps - w;
        float tau2 = fmaxf(ww2, kt);
        float e1b  = __expf(ww2 - tau2);
        float e2b  = __expf(kt - tau2);
        alpha = e1b*alpha + e2b*vt;
        beta  = e1b*beta + e2b;
        eps   = tau2;

        float sr = 1.0f / (1.0f + __expf(-rt));
        float uo = out * sr;
        __nv_bfloat16 h = __float2bfloat16(uo);
        g_uh[idx] = h;
        g_ul[idx] = __float2bfloat16(uo - __bfloat162float(h));
    }
}

// ---------------- launch ----------------
extern "C" void kernel_launch(void* const* d_in, const int* in_sizes, int n_in,
                              void* d_out, int out_size)
{
    const float* x  = (const float*)d_in[0];
    const float* td = (const float*)d_in[1];
    const float* tf = (const float*)d_in[2];
    const float* mk = (const float*)d_in[3];
    const float* mv = (const float*)d_in[4];
    const float* mr = (const float*)d_in[5];
    const float* Wk = (const float*)d_in[6];
    const float* Wv = (const float*)d_in[7];
    const float* Wr = (const float*)d_in[8];
    const float* Wo = (const float*)d_in[9];
    float* out = (float*)d_out;

    __nv_bfloat16 *xh, *xl, *wh, *wl, *uh, *ul;
    float* kvr;
    cudaGetSymbolAddress((void**)&xh,  g_xh);
    cudaGetSymbolAddress((void**)&xl,  g_xl);
    cudaGetSymbolAddress((void**)&wh,  g_wh);
    cudaGetSymbolAddress((void**)&wl,  g_wl);
    cudaGetSymbolAddress((void**)&kvr, g_kvr);
    cudaGetSymbolAddress((void**)&uh,  g_uh);
    cudaGetSymbolAddress((void**)&ul,  g_ul);

    const int GEMM_SMEM = 2 * 4 * BM * BK * (int)sizeof(__nv_bfloat16);  // 65536
    cudaFuncSetAttribute(gemm_kernel, cudaFuncAttributeMaxDynamicSharedMemorySize, GEMM_SMEM);

    wconv_kernel<<<(unsigned)((4*DD + 255) / 256), 256>>>(Wk, Wv, Wr, Wo);
    mix_kernel<<<(unsigned)((MD + 255) / 256), 256>>>(x, mk, mv, mr);

    dim3 grid(D_ / BN, M_ / BM);   // (16, 64)
    for (int i = 0; i < 3; i++) {
        gemm_kernel<<<grid, 256, GEMM_SMEM>>>(xh + (size_t)i*MD, xl + (size_t)i*MD,
                                              wh + (size_t)i*DD, wl + (size_t)i*DD,
                                              kvr + (size_t)i*MD, M_, D_, D_);
    }

    wkv_chunk_kernel<<<BDN/256, 256>>>(kvr, kvr + MD, td);
    wkv_stitch_kernel<<<(B_*D_)/256, 256>>>(td);
    wkv_apply_kernel<<<BDN/256, 256>>>(kvr, kvr + MD, kvr + 2*MD, td, tf);

    gemm_kernel<<<grid, 256, GEMM_SMEM>>>(uh, ul, wh + 3*DD, wl + 3*DD,
                                          out, M_, D_, D_);
}